// round 9
// baseline (speedup 1.0000x reference)
#include <cuda_runtime.h>
#include <cuda_fp16.h>
#include <cstdint>

#define F_DIM 256
#define H_DIM 256
#define MAXN 50048
#define MAXE 1600512

// ---------------- scratch ----------------
__device__ __half g_xh[(size_t)MAXN * F_DIM];    // x in fp16
__device__ __half g_hh[(size_t)MAXN * F_DIM];    // h = x + agg, fp16
__device__ __half g_wh[H_DIM * F_DIM];           // W in fp16
__device__ int    g_count[MAXN];
__device__ int    g_start[MAXN];
__device__ int    g_cursor[MAXN];
__device__ int    g_srclist[MAXE];
__device__ int    g_total;
__device__ int    g_is64;
__device__ float  g_colsum[H_DIM];
__device__ float  g_colsumsq[H_DIM];
__device__ float  g_scale[H_DIM];
__device__ float  g_shift[H_DIM];

// ---------------- helpers ----------------
__device__ __forceinline__ int load_idx(const void* ei, int is64, long long pos) {
    if (is64) return (int)(((const long long*)ei)[pos]);
    return ((const int*)ei)[pos];
}
__device__ __forceinline__ uint32_t h2u(__half2 h) {
    return *(uint32_t*)&h;
}

// fp16 mma m16n8k16: D += A*B (fp32 accumulate)
__device__ __forceinline__ void mma16816(float4& d, const uint4 a, const uint2 b) {
    asm volatile(
        "mma.sync.aligned.m16n8k16.row.col.f32.f16.f16.f32 "
        "{%0,%1,%2,%3}, {%4,%5,%6,%7}, {%8,%9}, {%0,%1,%2,%3};"
        : "+f"(d.x), "+f"(d.y), "+f"(d.z), "+f"(d.w)
        : "r"(a.x), "r"(a.y), "r"(a.z), "r"(a.w), "r"(b.x), "r"(b.y));
}

__device__ __forceinline__ void acc8(float* a, uint4 v) {
    const __half2* h = (const __half2*)&v;
#pragma unroll
    for (int i = 0; i < 4; i++) {
        float2 f = __half22float2(h[i]);
        a[2 * i] += f.x;
        a[2 * i + 1] += f.y;
    }
}

// ---------------- prep kernels ----------------
__global__ void detect_kernel(const unsigned int* __restrict__ e) {
    __shared__ int nz;
    if (threadIdx.x == 0) nz = 0;
    __syncthreads();
    unsigned int v = e[threadIdx.x * 2 + 1];
    if (v != 0u) atomicAdd(&nz, 1);
    __syncthreads();
    if (threadIdx.x == 0) g_is64 = (nz == 0) ? 1 : 0;
}

__global__ void zero_kernel(int N) {
    int i = blockIdx.x * blockDim.x + threadIdx.x;
    if (i < N) g_count[i] = 0;
    if (i < H_DIM) { g_colsum[i] = 0.0f; g_colsumsq[i] = 0.0f; }
    if (i == 0) g_total = 0;
}

__global__ void wconv_kernel(const float* __restrict__ W) {
    int i = blockIdx.x * blockDim.x + threadIdx.x;
    g_wh[i] = __float2half_rn(W[i]);
}

// x (fp32) -> fp16, vectorized
__global__ void xconv_kernel(const float4* __restrict__ x4, int n4) {
    for (int i = blockIdx.x * blockDim.x + threadIdx.x; i < n4;
         i += gridDim.x * blockDim.x) {
        float4 v = x4[i];
        __half2 h0 = __floats2half2_rn(v.x, v.y);
        __half2 h1 = __floats2half2_rn(v.z, v.w);
        ((uint2*)g_xh)[i] = make_uint2(h2u(h0), h2u(h1));
    }
}

__global__ void hist_kernel(const void* __restrict__ ei, int E) {
    int is64 = g_is64;
    for (int e = blockIdx.x * blockDim.x + threadIdx.x; e < E;
         e += gridDim.x * blockDim.x) {
        int d = load_idx(ei, is64, (long long)E + e);
        atomicAdd(&g_count[d], 1);
    }
}

__global__ void alloc_kernel(int N) {
    int i = blockIdx.x * blockDim.x + threadIdx.x;
    if (i < N) {
        int c = g_count[i];
        int s = atomicAdd(&g_total, c);
        g_start[i] = s;
        g_cursor[i] = s;
    }
}

__global__ void scatter_kernel(const void* __restrict__ ei, int E) {
    int is64 = g_is64;
    for (int e = blockIdx.x * blockDim.x + threadIdx.x; e < E;
         e += gridDim.x * blockDim.x) {
        int s = load_idx(ei, is64, e);
        int d = load_idx(ei, is64, (long long)E + e);
        int p = atomicAdd(&g_cursor[d], 1);
        g_srclist[p] = s;
    }
}

// Warp-per-node gather in fp16: h[d] = x[d] + sum_{s in N(d)} x[s]
// Each lane covers 8 features (one uint4 = 8 halves) of the 256-feature row.
__global__ void gather_kernel(int N) {
    int lane = threadIdx.x & 31;
    int warp = (blockIdx.x * blockDim.x + threadIdx.x) >> 5;
    int nwarps = (gridDim.x * blockDim.x) >> 5;
    const uint4* xv = (const uint4*)g_xh;
    uint4* hv = (uint4*)g_hh;
    for (int d = warp; d < N; d += nwarps) {
        float a[8];
#pragma unroll
        for (int j = 0; j < 8; j++) a[j] = 0.0f;
        acc8(a, xv[(size_t)d * 32 + lane]);

        int s = g_start[d];
        int c = g_count[d];
        const int* lst = g_srclist + s;
        int i = 0;
        for (; i + 4 <= c; i += 4) {
            int n0 = lst[i], n1 = lst[i + 1], n2 = lst[i + 2], n3 = lst[i + 3];
            uint4 v0 = xv[(size_t)n0 * 32 + lane];
            uint4 v1 = xv[(size_t)n1 * 32 + lane];
            uint4 v2 = xv[(size_t)n2 * 32 + lane];
            uint4 v3 = xv[(size_t)n3 * 32 + lane];
            acc8(a, v0); acc8(a, v1); acc8(a, v2); acc8(a, v3);
        }
        for (; i < c; i++) acc8(a, xv[(size_t)lst[i] * 32 + lane]);

        uint4 o;
        __half2 h0 = __floats2half2_rn(a[0], a[1]);
        __half2 h1 = __floats2half2_rn(a[2], a[3]);
        __half2 h2 = __floats2half2_rn(a[4], a[5]);
        __half2 h3 = __floats2half2_rn(a[6], a[7]);
        o.x = h2u(h0); o.y = h2u(h1);
        o.z = h2u(h2); o.w = h2u(h3);
        hv[(size_t)d * 32 + lane] = o;
    }
}

// ---------------- fp16 mma GEMM ----------------
// out[n][h] = sum_f h[n][f] * W[h][f] + b[h], fused BN stats.
// CTA 128x256, 8 warps (2m x 4n), warp tile 64x64, K chunks of 64 feats.
// Smem fragment-permuted, unit = half2 (4B):
//   A: tile(mt,kt) base (mt*4+kt)*512B; lane*16B -> {a0,a1,a2,a3}
//   B: tile(nt,kt) base (nt*4+kt)*256B; lane*8B  -> {b0,b1}
#define A_BYTES 16384
#define B_BYTES 32768
#define STAGE_BYTES (A_BYTES + B_BYTES)
#define SM_TOTAL (2 * STAGE_BYTES)

__device__ __forceinline__ void ldg_chunk(int row0, int ck, int N,
                                          uint4 (&ar)[4], uint4 (&br)[8]) {
    int tid = threadIdx.x;
    const uint4* hsrc = (const uint4*)g_hh;
    const uint4* wsrc = (const uint4*)g_wh;
#pragma unroll
    for (int i = 0; i < 4; i++) {
        int idx = tid + i * 256;           // 1024: row = idx>>3, u4 = idx&7
        int row = row0 + (idx >> 3);
        ar[i] = (row < N) ? hsrc[(size_t)row * 32 + ck * 8 + (idx & 7)]
                          : make_uint4(0, 0, 0, 0);
    }
#pragma unroll
    for (int i = 0; i < 8; i++) {
        int idx = tid + i * 256;           // 2048: n = idx>>3, u4 = idx&7
        br[i] = wsrc[(size_t)(idx >> 3) * 32 + ck * 8 + (idx & 7)];
    }
}

__device__ __forceinline__ void sts_chunk(char* sm, uint32_t abase, uint32_t bbase,
                                          const uint4 (&ar)[4], const uint4 (&br)[8]) {
    int tid = threadIdx.x;
#pragma unroll
    for (int i = 0; i < 4; i++) {
        int idx = tid + i * 256;
        int row = idx >> 3, f = idx & 7;   // f: unit-quad index (4 half2 units)
        int mt = row >> 4, rr = row & 15;
        int kt = f >> 1;
        int reg = (rr >> 3) + 2 * (f & 1);
        uint32_t base = abase + (uint32_t)((mt * 4 + kt) * 512 + reg * 4 +
                                           (rr & 7) * 64);
        const uint32_t* v = (const uint32_t*)&ar[i];
#pragma unroll
        for (int j = 0; j < 4; j++)
            *(uint32_t*)(sm + base + j * 16) = v[j];
    }
#pragma unroll
    for (int i = 0; i < 8; i++) {
        int idx = tid + i * 256;
        int n = idx >> 3, f = idx & 7;
        int nt = n >> 3, nn = n & 7;
        int kt = f >> 1;
        int reg = f & 1;
        uint32_t base = bbase + (uint32_t)((nt * 4 + kt) * 256 + reg * 4 + nn * 32);
        const uint32_t* v = (const uint32_t*)&br[i];
#pragma unroll
        for (int j = 0; j < 4; j++)
            *(uint32_t*)(sm + base + j * 8) = v[j];
    }
}

__global__ void __launch_bounds__(256, 1)
gemm_mma_kernel(const float* __restrict__ bias, float* __restrict__ out, int N) {
    extern __shared__ char sm[];
    int tid = threadIdx.x;
    int lane = tid & 31;
    int wid = tid >> 5;
    int wm = wid >> 2;
    int wn = wid & 3;
    int row0 = blockIdx.x * 128;

    float4 acc[4][8];
#pragma unroll
    for (int m = 0; m < 4; m++)
#pragma unroll
        for (int n = 0; n < 8; n++) acc[m][n] = make_float4(0.f, 0.f, 0.f, 0.f);

    uint4 ar[4];
    uint4 br[8];

    ldg_chunk(row0, 0, N, ar, br);
    sts_chunk(sm, 0, A_BYTES, ar, br);
    __syncthreads();

#pragma unroll 1
    for (int c = 0; c < 4; c++) {
        if (c < 3) ldg_chunk(row0, c + 1, N, ar, br);

        uint32_t ab = (c & 1) ? (uint32_t)STAGE_BYTES : 0u;
        uint32_t bb = ab + A_BYTES;
#pragma unroll
        for (int kt = 0; kt < 4; kt++) {
            uint4 af[4];
            uint2 bf[8];
#pragma unroll
            for (int m = 0; m < 4; m++)
                af[m] = *(const uint4*)(sm + ab +
                                        ((wm * 4 + m) * 4 + kt) * 512 + lane * 16);
#pragma unroll
            for (int n = 0; n < 8; n++)
                bf[n] = *(const uint2*)(sm + bb +
                                        ((wn * 8 + n) * 4 + kt) * 256 + lane * 8);
#pragma unroll
            for (int m = 0; m < 4; m++)
#pragma unroll
                for (int n = 0; n < 8; n++) mma16816(acc[m][n], af[m], bf[n]);
        }

        if (c < 3) {
            uint32_t nab = ((c + 1) & 1) ? (uint32_t)STAGE_BYTES : 0u;
            sts_chunk(sm, nab, nab + A_BYTES, ar, br);
        }
        __syncthreads();
    }

    // ---------------- epilogue: bias + store + BN stats ----------------
    float2 bv[8];
#pragma unroll
    for (int n = 0; n < 8; n++)
        bv[n] = *(const float2*)(bias + wn * 64 + n * 8 + 2 * (lane & 3));

    float s0[8], s1[8], q0[8], q1[8];
#pragma unroll
    for (int n = 0; n < 8; n++) { s0[n] = s1[n] = q0[n] = q1[n] = 0.f; }

#pragma unroll
    for (int m = 0; m < 4; m++) {
        int r0g = row0 + wm * 64 + m * 16 + (lane >> 2);
        bool v0 = (r0g < N);
        bool v8 = (r0g + 8 < N);
#pragma unroll
        for (int n = 0; n < 8; n++) {
            int col = wn * 64 + n * 8 + 2 * (lane & 3);
            float x0 = acc[m][n].x + bv[n].x;
            float x1 = acc[m][n].y + bv[n].y;
            float x2 = acc[m][n].z + bv[n].x;
            float x3 = acc[m][n].w + bv[n].y;
            if (v0) {
                *(float2*)(out + (size_t)r0g * H_DIM + col) = make_float2(x0, x1);
                s0[n] += x0; s1[n] += x1;
                q0[n] += x0 * x0; q1[n] += x1 * x1;
            }
            if (v8) {
                *(float2*)(out + (size_t)(r0g + 8) * H_DIM + col) = make_float2(x2, x3);
                s0[n] += x2; s1[n] += x3;
                q0[n] += x2 * x2; q1[n] += x3 * x3;
            }
        }
    }

#pragma unroll
    for (int n = 0; n < 8; n++) {
#pragma unroll
        for (int off = 16; off >= 4; off >>= 1) {
            s0[n] += __shfl_down_sync(0xffffffffu, s0[n], off);
            s1[n] += __shfl_down_sync(0xffffffffu, s1[n], off);
            q0[n] += __shfl_down_sync(0xffffffffu, q0[n], off);
            q1[n] += __shfl_down_sync(0xffffffffu, q1[n], off);
        }
        if (lane < 4) {
            int col = wn * 64 + n * 8 + 2 * lane;
            atomicAdd(&g_colsum[col], s0[n]);
            atomicAdd(&g_colsum[col + 1], s1[n]);
            atomicAdd(&g_colsumsq[col], q0[n]);
            atomicAdd(&g_colsumsq[col + 1], q1[n]);
        }
    }
}

// ---------------- BN finalize / normalize ----------------
__global__ void bn_finalize_kernel(const float* __restrict__ bn_w,
                                   const float* __restrict__ bn_b, int N) {
    int c = threadIdx.x;
    if (c < H_DIM) {
        float inv = 1.0f / (float)N;
        float mean = g_colsum[c] * inv;
        float var = g_colsumsq[c] * inv - mean * mean;
        float sc = bn_w[c] * rsqrtf(var + 1e-5f);
        g_scale[c] = sc;
        g_shift[c] = bn_b[c] - mean * sc;
    }
}

__global__ void normalize_kernel(float4* __restrict__ out, int n4) {
    const float4* sc4 = (const float4*)g_scale;
    const float4* sh4 = (const float4*)g_shift;
    for (int i = blockIdx.x * blockDim.x + threadIdx.x; i < n4;
         i += gridDim.x * blockDim.x) {
        float4 v = out[i];
        int c = i & 63;
        float4 sc = sc4[c];
        float4 sh = sh4[c];
        v.x = v.x * sc.x + sh.x;
        v.y = v.y * sc.y + sh.y;
        v.z = v.z * sc.z + sh.z;
        v.w = v.w * sc.w + sh.w;
        out[i] = v;
    }
}

// ---------------- launch ----------------
extern "C" void kernel_launch(void* const* d_in, const int* in_sizes, int n_in,
                              void* d_out, int out_size) {
    const float* x = (const float*)d_in[0];
    const void* ei = d_in[1];
    const float* W = (const float*)d_in[2];
    const float* b = (const float*)d_in[3];
    const float* bn_w = (const float*)d_in[4];
    const float* bn_b = (const float*)d_in[5];
    float* out = (float*)d_out;

    int N = in_sizes[0] / F_DIM;
    int E = in_sizes[1] / 2;
    int grid_m = (N + 127) / 128;

    cudaFuncSetAttribute(gemm_mma_kernel,
                         cudaFuncAttributeMaxDynamicSharedMemorySize, SM_TOTAL);

    detect_kernel<<<1, 256>>>((const unsigned int*)ei);
    zero_kernel<<<(N + 255) / 256, 256>>>(N);
    wconv_kernel<<<(H_DIM * F_DIM) / 256, 256>>>(W);
    xconv_kernel<<<2048, 256>>>((const float4*)x, N * (F_DIM / 4));
    hist_kernel<<<2048, 256>>>(ei, E);
    alloc_kernel<<<(N + 255) / 256, 256>>>(N);
    scatter_kernel<<<2048, 256>>>(ei, E);
    gather_kernel<<<6272, 256>>>(N);

    gemm_mma_kernel<<<grid_m, 256, SM_TOTAL>>>(b, out, N);
    bn_finalize_kernel<<<1, 256>>>(bn_w, bn_b, N);
    normalize_kernel<<<2048, 256>>>((float4*)out, N * (F_DIM / 4));
}

// round 10
// speedup vs baseline: 1.2798x; 1.2798x over previous
#include <cuda_runtime.h>
#include <cuda_fp16.h>
#include <cstdint>

#define F_DIM 256
#define H_DIM 256
#define MAXN 50048
#define MAXE 1600512

// ---------------- scratch ----------------
__device__ __half g_hh[(size_t)MAXN * F_DIM];    // h = x + agg, fp16
__device__ __half g_wh[H_DIM * F_DIM];           // W in fp16
__device__ int    g_count[MAXN];
__device__ int    g_start[MAXN];
__device__ int    g_cursor[MAXN];
__device__ int    g_srclist[MAXE];
__device__ int    g_total;
__device__ int    g_is64;
__device__ float  g_colsum[H_DIM];
__device__ float  g_colsumsq[H_DIM];
__device__ float  g_scale[H_DIM];
__device__ float  g_shift[H_DIM];

// ---------------- helpers ----------------
__device__ __forceinline__ float4 f4add(float4 a, float4 b) {
    a.x += b.x; a.y += b.y; a.z += b.z; a.w += b.w; return a;
}
__device__ __forceinline__ int load_idx(const void* ei, int is64, long long pos) {
    if (is64) return (int)(((const long long*)ei)[pos]);
    return ((const int*)ei)[pos];
}
__device__ __forceinline__ uint32_t h2u(__half2 h) {
    return *(uint32_t*)&h;
}

// fp16 mma m16n8k16: D += A*B (fp32 accumulate)
__device__ __forceinline__ void mma16816(float4& d, const uint4 a, const uint2 b) {
    asm volatile(
        "mma.sync.aligned.m16n8k16.row.col.f32.f16.f16.f32 "
        "{%0,%1,%2,%3}, {%4,%5,%6,%7}, {%8,%9}, {%0,%1,%2,%3};"
        : "+f"(d.x), "+f"(d.y), "+f"(d.z), "+f"(d.w)
        : "r"(a.x), "r"(a.y), "r"(a.z), "r"(a.w), "r"(b.x), "r"(b.y));
}

// ---------------- prep kernels ----------------
// launch index 0
__global__ void detect_kernel(const unsigned int* __restrict__ e) {
    __shared__ int nz;
    if (threadIdx.x == 0) nz = 0;
    __syncthreads();
    unsigned int v = e[threadIdx.x * 2 + 1];
    if (v != 0u) atomicAdd(&nz, 1);
    __syncthreads();
    if (threadIdx.x == 0) g_is64 = (nz == 0) ? 1 : 0;
}

// launch index 1: zero counters + stats, convert W to fp16. grid 256x256.
__global__ void init_kernel(const float* __restrict__ W, int N) {
    int i = blockIdx.x * blockDim.x + threadIdx.x;
    if (i < N) g_count[i] = 0;
    if (i < H_DIM) { g_colsum[i] = 0.0f; g_colsumsq[i] = 0.0f; }
    if (i == 0) g_total = 0;
    if (i < H_DIM * F_DIM) g_wh[i] = __float2half_rn(W[i]);
}

// launch index 2
__global__ void hist_kernel(const void* __restrict__ ei, int E) {
    int is64 = g_is64;
    for (int e = blockIdx.x * blockDim.x + threadIdx.x; e < E;
         e += gridDim.x * blockDim.x) {
        int d = load_idx(ei, is64, (long long)E + e);
        atomicAdd(&g_count[d], 1);
    }
}

// launch index 3
__global__ void alloc_kernel(int N) {
    int i = blockIdx.x * blockDim.x + threadIdx.x;
    if (i < N) {
        int c = g_count[i];
        int s = atomicAdd(&g_total, c);
        g_start[i] = s;
        g_cursor[i] = s;
    }
}

// launch index 4
__global__ void scatter_kernel(const void* __restrict__ ei, int E) {
    int is64 = g_is64;
    for (int e = blockIdx.x * blockDim.x + threadIdx.x; e < E;
         e += gridDim.x * blockDim.x) {
        int s = load_idx(ei, is64, e);
        int d = load_idx(ei, is64, (long long)E + e);
        int p = atomicAdd(&g_cursor[d], 1);
        g_srclist[p] = s;
    }
}

// launch index 5: warp-per-node gather.
// Reads fp32 x, accumulates fp32, writes fp16 h (pack once at end).
__global__ void gather_kernel(const float4* __restrict__ x4, int N) {
    int lane = threadIdx.x & 31;
    int warp = (blockIdx.x * blockDim.x + threadIdx.x) >> 5;
    int nwarps = (gridDim.x * blockDim.x) >> 5;
    for (int d = warp; d < N; d += nwarps) {
        const float4* xd = x4 + (size_t)d * 64;
        float4 a0 = xd[lane];
        float4 a1 = xd[lane + 32];
        int s = g_start[d];
        int c = g_count[d];
        const int* lst = g_srclist + s;
        int i = 0;
        for (; i + 8 <= c; i += 8) {
            float4 v0[8], v1[8];
#pragma unroll
            for (int j = 0; j < 8; j++) {
                const float4* p = x4 + (size_t)lst[i + j] * 64;
                v0[j] = p[lane];
                v1[j] = p[lane + 32];
            }
#pragma unroll
            for (int j = 0; j < 8; j++) {
                a0 = f4add(a0, v0[j]);
                a1 = f4add(a1, v1[j]);
            }
        }
        for (; i < c; i++) {
            const float4* p = x4 + (size_t)lst[i] * 64;
            a0 = f4add(a0, p[lane]);
            a1 = f4add(a1, p[lane + 32]);
        }
        __half2 h0 = __floats2half2_rn(a0.x, a0.y);
        __half2 h1 = __floats2half2_rn(a0.z, a0.w);
        __half2 h2 = __floats2half2_rn(a1.x, a1.y);
        __half2 h3 = __floats2half2_rn(a1.z, a1.w);
        uint2* hrow = (uint2*)(g_hh + (size_t)d * F_DIM);
        hrow[lane] = make_uint2(h2u(h0), h2u(h1));
        hrow[32 + lane] = make_uint2(h2u(h2), h2u(h3));
    }
}

// ---------------- fp16 mma GEMM (launch index 6) ----------------
// out[n][h] = sum_f h[n][f] * W[h][f] + b[h], fused BN stats.
// CTA 128x256, 8 warps (2m x 4n), warp tile 64x64, K chunks of 64 feats.
#define A_BYTES 16384
#define B_BYTES 32768
#define STAGE_BYTES (A_BYTES + B_BYTES)
#define SM_TOTAL (2 * STAGE_BYTES)

__device__ __forceinline__ void ldg_chunk(int row0, int ck, int N,
                                          uint4 (&ar)[4], uint4 (&br)[8]) {
    int tid = threadIdx.x;
    const uint4* hsrc = (const uint4*)g_hh;
    const uint4* wsrc = (const uint4*)g_wh;
#pragma unroll
    for (int i = 0; i < 4; i++) {
        int idx = tid + i * 256;           // 1024: row = idx>>3, u4 = idx&7
        int row = row0 + (idx >> 3);
        ar[i] = (row < N) ? hsrc[(size_t)row * 32 + ck * 8 + (idx & 7)]
                          : make_uint4(0, 0, 0, 0);
    }
#pragma unroll
    for (int i = 0; i < 8; i++) {
        int idx = tid + i * 256;           // 2048: n = idx>>3, u4 = idx&7
        br[i] = wsrc[(size_t)(idx >> 3) * 32 + ck * 8 + (idx & 7)];
    }
}

__device__ __forceinline__ void sts_chunk(char* sm, uint32_t abase, uint32_t bbase,
                                          const uint4 (&ar)[4], const uint4 (&br)[8]) {
    int tid = threadIdx.x;
#pragma unroll
    for (int i = 0; i < 4; i++) {
        int idx = tid + i * 256;
        int row = idx >> 3, f = idx & 7;
        int mt = row >> 4, rr = row & 15;
        int kt = f >> 1;
        int reg = (rr >> 3) + 2 * (f & 1);
        uint32_t base = abase + (uint32_t)((mt * 4 + kt) * 512 + reg * 4 +
                                           (rr & 7) * 64);
        const uint32_t* v = (const uint32_t*)&ar[i];
#pragma unroll
        for (int j = 0; j < 4; j++)
            *(uint32_t*)(sm + base + j * 16) = v[j];
    }
#pragma unroll
    for (int i = 0; i < 8; i++) {
        int idx = tid + i * 256;
        int n = idx >> 3, f = idx & 7;
        int nt = n >> 3, nn = n & 7;
        int kt = f >> 1;
        int reg = f & 1;
        uint32_t base = bbase + (uint32_t)((nt * 4 + kt) * 256 + reg * 4 + nn * 32);
        const uint32_t* v = (const uint32_t*)&br[i];
#pragma unroll
        for (int j = 0; j < 4; j++)
            *(uint32_t*)(sm + base + j * 8) = v[j];
    }
}

__global__ void __launch_bounds__(256, 1)
gemm_mma_kernel(const float* __restrict__ bias, float* __restrict__ out, int N) {
    extern __shared__ char sm[];
    int tid = threadIdx.x;
    int lane = tid & 31;
    int wid = tid >> 5;
    int wm = wid >> 2;
    int wn = wid & 3;
    int row0 = blockIdx.x * 128;

    float4 acc[4][8];
#pragma unroll
    for (int m = 0; m < 4; m++)
#pragma unroll
        for (int n = 0; n < 8; n++) acc[m][n] = make_float4(0.f, 0.f, 0.f, 0.f);

    uint4 ar[4];
    uint4 br[8];

    ldg_chunk(row0, 0, N, ar, br);
    sts_chunk(sm, 0, A_BYTES, ar, br);
    __syncthreads();

#pragma unroll 1
    for (int c = 0; c < 4; c++) {
        if (c < 3) ldg_chunk(row0, c + 1, N, ar, br);

        uint32_t ab = (c & 1) ? (uint32_t)STAGE_BYTES : 0u;
        uint32_t bb = ab + A_BYTES;
#pragma unroll
        for (int kt = 0; kt < 4; kt++) {
            uint4 af[4];
            uint2 bf[8];
#pragma unroll
            for (int m = 0; m < 4; m++)
                af[m] = *(const uint4*)(sm + ab +
                                        ((wm * 4 + m) * 4 + kt) * 512 + lane * 16);
#pragma unroll
            for (int n = 0; n < 8; n++)
                bf[n] = *(const uint2*)(sm + bb +
                                        ((wn * 8 + n) * 4 + kt) * 256 + lane * 8);
#pragma unroll
            for (int m = 0; m < 4; m++)
#pragma unroll
                for (int n = 0; n < 8; n++) mma16816(acc[m][n], af[m], bf[n]);
        }

        if (c < 3) {
            uint32_t nab = ((c + 1) & 1) ? (uint32_t)STAGE_BYTES : 0u;
            sts_chunk(sm, nab, nab + A_BYTES, ar, br);
        }
        __syncthreads();
    }

    // ---------------- epilogue: bias + store + BN stats ----------------
    float2 bv[8];
#pragma unroll
    for (int n = 0; n < 8; n++)
        bv[n] = *(const float2*)(bias + wn * 64 + n * 8 + 2 * (lane & 3));

    float s0[8], s1[8], q0[8], q1[8];
#pragma unroll
    for (int n = 0; n < 8; n++) { s0[n] = s1[n] = q0[n] = q1[n] = 0.f; }

#pragma unroll
    for (int m = 0; m < 4; m++) {
        int r0g = row0 + wm * 64 + m * 16 + (lane >> 2);
        bool v0 = (r0g < N);
        bool v8 = (r0g + 8 < N);
#pragma unroll
        for (int n = 0; n < 8; n++) {
            int col = wn * 64 + n * 8 + 2 * (lane & 3);
            float x0 = acc[m][n].x + bv[n].x;
            float x1 = acc[m][n].y + bv[n].y;
            float x2 = acc[m][n].z + bv[n].x;
            float x3 = acc[m][n].w + bv[n].y;
            if (v0) {
                *(float2*)(out + (size_t)r0g * H_DIM + col) = make_float2(x0, x1);
                s0[n] += x0; s1[n] += x1;
                q0[n] += x0 * x0; q1[n] += x1 * x1;
            }
            if (v8) {
                *(float2*)(out + (size_t)(r0g + 8) * H_DIM + col) = make_float2(x2, x3);
                s0[n] += x2; s1[n] += x3;
                q0[n] += x2 * x2; q1[n] += x3 * x3;
            }
        }
    }

#pragma unroll
    for (int n = 0; n < 8; n++) {
#pragma unroll
        for (int off = 16; off >= 4; off >>= 1) {
            s0[n] += __shfl_down_sync(0xffffffffu, s0[n], off);
            s1[n] += __shfl_down_sync(0xffffffffu, s1[n], off);
            q0[n] += __shfl_down_sync(0xffffffffu, q0[n], off);
            q1[n] += __shfl_down_sync(0xffffffffu, q1[n], off);
        }
        if (lane < 4) {
            int col = wn * 64 + n * 8 + 2 * lane;
            atomicAdd(&g_colsum[col], s0[n]);
            atomicAdd(&g_colsum[col + 1], s1[n]);
            atomicAdd(&g_colsumsq[col], q0[n]);
            atomicAdd(&g_colsumsq[col + 1], q1[n]);
        }
    }
}

// ---------------- BN finalize / normalize ----------------
__global__ void bn_finalize_kernel(const float* __restrict__ bn_w,
                                   const float* __restrict__ bn_b, int N) {
    int c = threadIdx.x;
    if (c < H_DIM) {
        float inv = 1.0f / (float)N;
        float mean = g_colsum[c] * inv;
        float var = g_colsumsq[c] * inv - mean * mean;
        float sc = bn_w[c] * rsqrtf(var + 1e-5f);
        g_scale[c] = sc;
        g_shift[c] = bn_b[c] - mean * sc;
    }
}

__global__ void normalize_kernel(float4* __restrict__ out, int n4) {
    const float4* sc4 = (const float4*)g_scale;
    const float4* sh4 = (const float4*)g_shift;
    for (int i = blockIdx.x * blockDim.x + threadIdx.x; i < n4;
         i += gridDim.x * blockDim.x) {
        float4 v = out[i];
        int c = i & 63;
        float4 sc = sc4[c];
        float4 sh = sh4[c];
        v.x = v.x * sc.x + sh.x;
        v.y = v.y * sc.y + sh.y;
        v.z = v.z * sc.z + sh.z;
        v.w = v.w * sc.w + sh.w;
        out[i] = v;
    }
}

// ---------------- launch ----------------
extern "C" void kernel_launch(void* const* d_in, const int* in_sizes, int n_in,
                              void* d_out, int out_size) {
    const float* x = (const float*)d_in[0];
    const void* ei = d_in[1];
    const float* W = (const float*)d_in[2];
    const float* b = (const float*)d_in[3];
    const float* bn_w = (const float*)d_in[4];
    const float* bn_b = (const float*)d_in[5];
    float* out = (float*)d_out;

    int N = in_sizes[0] / F_DIM;
    int E = in_sizes[1] / 2;
    int grid_m = (N + 127) / 128;

    cudaFuncSetAttribute(gemm_mma_kernel,
                         cudaFuncAttributeMaxDynamicSharedMemorySize, SM_TOTAL);

    detect_kernel<<<1, 256>>>((const unsigned int*)ei);           // 0
    init_kernel<<<256, 256>>>(W, N);                              // 1
    hist_kernel<<<2048, 256>>>(ei, E);                            // 2
    alloc_kernel<<<(N + 255) / 256, 256>>>(N);                    // 3
    scatter_kernel<<<2048, 256>>>(ei, E);                         // 4
    gather_kernel<<<6272, 256>>>((const float4*)x, N);            // 5 (ncu -s 5)
    gemm_mma_kernel<<<grid_m, 256, SM_TOTAL>>>(b, out, N);        // 6
    bn_finalize_kernel<<<1, 256>>>(bn_w, bn_b, N);                // 7
    normalize_kernel<<<2048, 256>>>((float4*)out, N * (F_DIM / 4)); // 8
}

// round 12
// speedup vs baseline: 1.5629x; 1.2212x over previous
#include <cuda_runtime.h>
#include <cuda_fp16.h>
#include <cstdint>

#define F_DIM 256
#define H_DIM 256
#define MAXN 50048
#define MAXE 1600512

// ---------------- scratch ----------------
__device__ __half g_xh[(size_t)MAXN * F_DIM];    // x in fp16
__device__ __half g_hh[(size_t)MAXN * F_DIM];    // h = x + agg, fp16
__device__ __half g_wh[H_DIM * F_DIM];           // W in fp16
__device__ int    g_count[MAXN];
__device__ int    g_start[MAXN];
__device__ int    g_cursor[MAXN];
__device__ int    g_srclist[MAXE];
__device__ int    g_total;
__device__ int    g_is64;
__device__ float  g_colsum[H_DIM];
__device__ float  g_colsumsq[H_DIM];
__device__ float  g_scale[H_DIM];
__device__ float  g_shift[H_DIM];

// ---------------- helpers ----------------
__device__ __forceinline__ int load_idx(const void* ei, int is64, long long pos) {
    if (is64) return (int)(((const long long*)ei)[pos]);
    return ((const int*)ei)[pos];
}
__device__ __forceinline__ uint32_t h2u(__half2 h) {
    return *(uint32_t*)&h;
}

// fp16 mma m16n8k16: D += A*B (fp32 accumulate)
__device__ __forceinline__ void mma16816(float4& d, const uint4 a, const uint2 b) {
    asm volatile(
        "mma.sync.aligned.m16n8k16.row.col.f32.f16.f16.f32 "
        "{%0,%1,%2,%3}, {%4,%5,%6,%7}, {%8,%9}, {%0,%1,%2,%3};"
        : "+f"(d.x), "+f"(d.y), "+f"(d.z), "+f"(d.w)
        : "r"(a.x), "r"(a.y), "r"(a.z), "r"(a.w), "r"(b.x), "r"(b.y));
}

// add fp16 pair-sum of two uint4 (8 halves each) into fp32 accumulators
__device__ __forceinline__ void addpair(float* a, uint4 u, uint4 v) {
    const __half2* hu = (const __half2*)&u;
    const __half2* hv = (const __half2*)&v;
#pragma unroll
    for (int k = 0; k < 4; k++) {
        __half2 s = __hadd2(hu[k], hv[k]);
        float2 f = __half22float2(s);
        a[2 * k] += f.x;
        a[2 * k + 1] += f.y;
    }
}
__device__ __forceinline__ void addone(float* a, uint4 u) {
    const __half2* hu = (const __half2*)&u;
#pragma unroll
    for (int k = 0; k < 4; k++) {
        float2 f = __half22float2(hu[k]);
        a[2 * k] += f.x;
        a[2 * k + 1] += f.y;
    }
}

// ---------------- prep kernels ----------------
// launch 0: detect int64 vs int32 (block 0), zero counters/stats, W -> fp16
__global__ void init_kernel(const unsigned int* __restrict__ e,
                            const float* __restrict__ W, int N) {
    int i = blockIdx.x * blockDim.x + threadIdx.x;
    if (blockIdx.x == 0) {
        __shared__ int nz;
        if (threadIdx.x == 0) nz = 0;
        __syncthreads();
        unsigned int v = e[threadIdx.x * 2 + 1];
        if (v != 0u) atomicAdd(&nz, 1);
        __syncthreads();
        if (threadIdx.x == 0) g_is64 = (nz == 0) ? 1 : 0;
    }
    if (i < N) g_count[i] = 0;
    if (i < H_DIM) { g_colsum[i] = 0.0f; g_colsumsq[i] = 0.0f; }
    if (i == 0) g_total = 0;
    if (i < H_DIM * F_DIM) g_wh[i] = __float2half_rn(W[i]);
}

// launch 1: blocks [0, XB) convert x -> fp16; blocks [XB, ...) histogram dsts.
#define XB 1024
__global__ void histxconv_kernel(const void* __restrict__ ei, int E,
                                 const float4* __restrict__ x4, int n4) {
    if (blockIdx.x < XB) {
        for (int i = blockIdx.x * blockDim.x + threadIdx.x; i < n4;
             i += XB * blockDim.x) {
            float4 v = x4[i];
            __half2 h0 = __floats2half2_rn(v.x, v.y);
            __half2 h1 = __floats2half2_rn(v.z, v.w);
            ((uint2*)g_xh)[i] = make_uint2(h2u(h0), h2u(h1));
        }
    } else {
        int is64 = g_is64;
        int nb = gridDim.x - XB;
        for (int e = (blockIdx.x - XB) * blockDim.x + threadIdx.x; e < E;
             e += nb * blockDim.x) {
            int d = load_idx(ei, is64, (long long)E + e);
            atomicAdd(&g_count[d], 1);
        }
    }
}

// launch 2
__global__ void alloc_kernel(int N) {
    int i = blockIdx.x * blockDim.x + threadIdx.x;
    if (i < N) {
        int c = g_count[i];
        int s = atomicAdd(&g_total, c);
        g_start[i] = s;
        g_cursor[i] = s;
    }
}

// launch 3
__global__ void scatter_kernel(const void* __restrict__ ei, int E) {
    int is64 = g_is64;
    for (int e = blockIdx.x * blockDim.x + threadIdx.x; e < E;
         e += gridDim.x * blockDim.x) {
        int s = load_idx(ei, is64, e);
        int d = load_idx(ei, is64, (long long)E + e);
        int p = atomicAdd(&g_cursor[d], 1);
        g_srclist[p] = s;
    }
}

// launch 4: warp-per-node gather over fp16 x.
// Per lane: one uint4 (8 halves = 8 features). Edge pairs summed with HADD2
// first (one fp16 rounding), then accumulated in fp32.
__global__ void gather_kernel(int N) {
    int lane = threadIdx.x & 31;
    int warp = (blockIdx.x * blockDim.x + threadIdx.x) >> 5;
    int nwarps = (gridDim.x * blockDim.x) >> 5;
    const uint4* xv = (const uint4*)g_xh;
    for (int d = warp; d < N; d += nwarps) {
        float a[8];
#pragma unroll
        for (int j = 0; j < 8; j++) a[j] = 0.0f;
        addone(a, xv[(size_t)d * 32 + lane]);   // self term x[d]

        int s = g_start[d];
        int c = g_count[d];
        const int* lst = g_srclist + s;
        int i = 0;
        for (; i + 8 <= c; i += 8) {
            uint4 v[8];
#pragma unroll
            for (int j = 0; j < 8; j++)
                v[j] = xv[(size_t)lst[i + j] * 32 + lane];
            addpair(a, v[0], v[1]);
            addpair(a, v[2], v[3]);
            addpair(a, v[4], v[5]);
            addpair(a, v[6], v[7]);
        }
        for (; i + 2 <= c; i += 2) {
            uint4 u = xv[(size_t)lst[i] * 32 + lane];
            uint4 v = xv[(size_t)lst[i + 1] * 32 + lane];
            addpair(a, u, v);
        }
        if (i < c) addone(a, xv[(size_t)lst[i] * 32 + lane]);

        __half2 h0 = __floats2half2_rn(a[0], a[1]);
        __half2 h1 = __floats2half2_rn(a[2], a[3]);
        __half2 h2 = __floats2half2_rn(a[4], a[5]);
        __half2 h3 = __floats2half2_rn(a[6], a[7]);
        uint4 o;
        o.x = h2u(h0); o.y = h2u(h1); o.z = h2u(h2); o.w = h2u(h3);
        ((uint4*)g_hh)[(size_t)d * 32 + lane] = o;   // 32 uint4 per 256-half row
    }
}

// ---------------- fp16 mma GEMM (launch 5) ----------------
#define A_BYTES 16384
#define B_BYTES 32768
#define STAGE_BYTES (A_BYTES + B_BYTES)
#define SM_TOTAL (2 * STAGE_BYTES)

__device__ __forceinline__ void ldg_chunk(int row0, int ck, int N,
                                          uint4 (&ar)[4], uint4 (&br)[8]) {
    int tid = threadIdx.x;
    const uint4* hsrc = (const uint4*)g_hh;
    const uint4* wsrc = (const uint4*)g_wh;
#pragma unroll
    for (int i = 0; i < 4; i++) {
        int idx = tid + i * 256;
        int row = row0 + (idx >> 3);
        ar[i] = (row < N) ? hsrc[(size_t)row * 32 + ck * 8 + (idx & 7)]
                          : make_uint4(0, 0, 0, 0);
    }
#pragma unroll
    for (int i = 0; i < 8; i++) {
        int idx = tid + i * 256;
        br[i] = wsrc[(size_t)(idx >> 3) * 32 + ck * 8 + (idx & 7)];
    }
}

__device__ __forceinline__ void sts_chunk(char* sm, uint32_t abase, uint32_t bbase,
                                          const uint4 (&ar)[4], const uint4 (&br)[8]) {
    int tid = threadIdx.x;
#pragma unroll
    for (int i = 0; i < 4; i++) {
        int idx = tid + i * 256;
        int row = idx >> 3, f = idx & 7;
        int mt = row >> 4, rr = row & 15;
        int kt = f >> 1;
        int reg = (rr >> 3) + 2 * (f & 1);
        uint32_t base = abase + (uint32_t)((mt * 4 + kt) * 512 + reg * 4 +
                                           (rr & 7) * 64);
        const uint32_t* v = (const uint32_t*)&ar[i];
#pragma unroll
        for (int j = 0; j < 4; j++)
            *(uint32_t*)(sm + base + j * 16) = v[j];
    }
#pragma unroll
    for (int i = 0; i < 8; i++) {
        int idx = tid + i * 256;
        int n = idx >> 3, f = idx & 7;
        int nt = n >> 3, nn = n & 7;
        int kt = f >> 1;
        int reg = f & 1;
        uint32_t base = bbase + (uint32_t)((nt * 4 + kt) * 256 + reg * 4 + nn * 32);
        const uint32_t* v = (const uint32_t*)&br[i];
#pragma unroll
        for (int j = 0; j < 4; j++)
            *(uint32_t*)(sm + base + j * 8) = v[j];
    }
}

__global__ void __launch_bounds__(256, 1)
gemm_mma_kernel(const float* __restrict__ bias, float* __restrict__ out, int N) {
    extern __shared__ char sm[];
    int tid = threadIdx.x;
    int lane = tid & 31;
    int wid = tid >> 5;
    int wm = wid >> 2;
    int wn = wid & 3;
    int row0 = blockIdx.x * 128;

    float4 acc[4][8];
#pragma unroll
    for (int m = 0; m < 4; m++)
#pragma unroll
        for (int n = 0; n < 8; n++) acc[m][n] = make_float4(0.f, 0.f, 0.f, 0.f);

    uint4 ar[4];
    uint4 br[8];

    ldg_chunk(row0, 0, N, ar, br);
    sts_chunk(sm, 0, A_BYTES, ar, br);
    __syncthreads();

#pragma unroll 1
    for (int c = 0; c < 4; c++) {
        if (c < 3) ldg_chunk(row0, c + 1, N, ar, br);

        uint32_t ab = (c & 1) ? (uint32_t)STAGE_BYTES : 0u;
        uint32_t bb = ab + A_BYTES;
#pragma unroll
        for (int kt = 0; kt < 4; kt++) {
            uint4 af[4];
            uint2 bf[8];
#pragma unroll
            for (int m = 0; m < 4; m++)
                af[m] = *(const uint4*)(sm + ab +
                                        ((wm * 4 + m) * 4 + kt) * 512 + lane * 16);
#pragma unroll
            for (int n = 0; n < 8; n++)
                bf[n] = *(const uint2*)(sm + bb +
                                        ((wn * 8 + n) * 4 + kt) * 256 + lane * 8);
#pragma unroll
            for (int m = 0; m < 4; m++)
#pragma unroll
                for (int n = 0; n < 8; n++) mma16816(acc[m][n], af[m], bf[n]);
        }

        if (c < 3) {
            uint32_t nab = ((c + 1) & 1) ? (uint32_t)STAGE_BYTES : 0u;
            sts_chunk(sm, nab, nab + A_BYTES, ar, br);
        }
        __syncthreads();
    }

    // epilogue: bias + store + BN stats
    float2 bv[8];
#pragma unroll
    for (int n = 0; n < 8; n++)
        bv[n] = *(const float2*)(bias + wn * 64 + n * 8 + 2 * (lane & 3));

    float s0[8], s1[8], q0[8], q1[8];
#pragma unroll
    for (int n = 0; n < 8; n++) { s0[n] = s1[n] = q0[n] = q1[n] = 0.f; }

#pragma unroll
    for (int m = 0; m < 4; m++) {
        int r0g = row0 + wm * 64 + m * 16 + (lane >> 2);
        bool v0 = (r0g < N);
        bool v8 = (r0g + 8 < N);
#pragma unroll
        for (int n = 0; n < 8; n++) {
            int col = wn * 64 + n * 8 + 2 * (lane & 3);
            float x0 = acc[m][n].x + bv[n].x;
            float x1 = acc[m][n].y + bv[n].y;
            float x2 = acc[m][n].z + bv[n].x;
            float x3 = acc[m][n].w + bv[n].y;
            if (v0) {
                *(float2*)(out + (size_t)r0g * H_DIM + col) = make_float2(x0, x1);
                s0[n] += x0; s1[n] += x1;
                q0[n] += x0 * x0; q1[n] += x1 * x1;
            }
            if (v8) {
                *(float2*)(out + (size_t)(r0g + 8) * H_DIM + col) = make_float2(x2, x3);
                s0[n] += x2; s1[n] += x3;
                q0[n] += x2 * x2; q1[n] += x3 * x3;
            }
        }
    }

#pragma unroll
    for (int n = 0; n < 8; n++) {
#pragma unroll
        for (int off = 16; off >= 4; off >>= 1) {
            s0[n] += __shfl_down_sync(0xffffffffu, s0[n], off);
            s1[n] += __shfl_down_sync(0xffffffffu, s1[n], off);
            q0[n] += __shfl_down_sync(0xffffffffu, q0[n], off);
            q1[n] += __shfl_down_sync(0xffffffffu, q1[n], off);
        }
        if (lane < 4) {
            int col = wn * 64 + n * 8 + 2 * lane;
            atomicAdd(&g_colsum[col], s0[n]);
            atomicAdd(&g_colsum[col + 1], s1[n]);
            atomicAdd(&g_colsumsq[col], q0[n]);
            atomicAdd(&g_colsumsq[col + 1], q1[n]);
        }
    }
}

// ---------------- BN finalize / normalize ----------------
__global__ void bn_finalize_kernel(const float* __restrict__ bn_w,
                                   const float* __restrict__ bn_b, int N) {
    int c = threadIdx.x;
    if (c < H_DIM) {
        float inv = 1.0f / (float)N;
        float mean = g_colsum[c] * inv;
        float var = g_colsumsq[c] * inv - mean * mean;
        float sc = bn_w[c] * rsqrtf(var + 1e-5f);
        g_scale[c] = sc;
        g_shift[c] = bn_b[c] - mean * sc;
    }
}

__global__ void normalize_kernel(float4* __restrict__ out, int n4) {
    const float4* sc4 = (const float4*)g_scale;
    const float4* sh4 = (const float4*)g_shift;
    for (int i = blockIdx.x * blockDim.x + threadIdx.x; i < n4;
         i += gridDim.x * blockDim.x) {
        float4 v = out[i];
        int c = i & 63;
        float4 sc = sc4[c];
        float4 sh = sh4[c];
        v.x = v.x * sc.x + sh.x;
        v.y = v.y * sc.y + sh.y;
        v.z = v.z * sc.z + sh.z;
        v.w = v.w * sc.w + sh.w;
        out[i] = v;
    }
}

// ---------------- launch ----------------
extern "C" void kernel_launch(void* const* d_in, const int* in_sizes, int n_in,
                              void* d_out, int out_size) {
    const float* x = (const float*)d_in[0];
    const void* ei = d_in[1];
    const float* W = (const float*)d_in[2];
    const float* b = (const float*)d_in[3];
    const float* bn_w = (const float*)d_in[4];
    const float* bn_b = (const float*)d_in[5];
    float* out = (float*)d_out;

    int N = in_sizes[0] / F_DIM;
    int E = in_sizes[1] / 2;
    int grid_m = (N + 127) / 128;

    cudaFuncSetAttribute(gemm_mma_kernel,
                         cudaFuncAttributeMaxDynamicSharedMemorySize, SM_TOTAL);

    init_kernel<<<256, 256>>>((const unsigned int*)ei, W, N);       // 0
    histxconv_kernel<<<XB + 1024, 256>>>(ei, E, (const float4*)x,   // 1
                                         N * (F_DIM / 4));
    alloc_kernel<<<(N + 255) / 256, 256>>>(N);                      // 2
    scatter_kernel<<<2048, 256>>>(ei, E);                           // 3
    gather_kernel<<<6272, 256>>>(N);                                // 4
    gemm_mma_kernel<<<grid_m, 256, SM_TOTAL>>>(b, out, N);          // 5
    bn_finalize_kernel<<<1, 256>>>(bn_w, bn_b, N);                  // 6
    normalize_kernel<<<2048, 256>>>((float4*)out, N * (F_DIM / 4)); // 7
}